// round 8
// baseline (speedup 1.0000x reference)
#include <cuda_runtime.h>

#define FULLMASK 0xffffffffu

constexpr int   B_     = 256;
constexpr int   T_     = 256;
constexpr int   C_     = 1024;
constexpr int   L_     = 32;
constexpr int   S_     = 65;      // 2*L+1 extended states
constexpr int   SP_    = 34;      // compact row: [blank, lab0..lab31, pad]
constexpr int   BLANK_ = C_ - 1;
constexpr float PRE    = 512.0f;  // 2^9 per-step prescale
constexpr int   PRE_E  = 9;
constexpr float EPS    = 1e-7f;
constexpr float EPS_S  = EPS * PRE;

constexpr int   NGATHER = B_ * 8;     // 2048 gather CTAs (batch-major)

// compact gathered probs (8.9 MB, L2-resident) + per-(batch,chunk) ready flags
__device__ float g_scr[(size_t)B_ * T_ * SP_];
__device__ int   g_cflag[B_][8];      // zero-init; self-resetting per run

__device__ __forceinline__ int kidx(int s) {
    return (s >= S_) ? 33 : ((s & 1) ? ((s >> 1) + 1) : 0);
}
__device__ __forceinline__ float allow_fwd(int s, const int* labs) {
    if (!(s & 1) || s >= S_) return 0.0f;
    const int j = (s - 1) >> 1;
    return (j == 0 || labs[j] != labs[j - 1]) ? 1.0f : 0.0f;
}
__device__ __forceinline__ float allow_bwd(int s, const int* labs) {
    if (!(s & 1) || (s + 2) > S_ - 1) return 0.0f;
    const int jn = (s + 1) >> 1, jp = (s - 1) >> 1;
    return (labs[jn] != labs[jp]) ? 1.0f : 0.0f;
}
__device__ __forceinline__ int renorm(float& r0, float& r1, float& r2) {
    float m = fmaxf(fmaxf(r0, r1), r2);
    int im = __float_as_int(m);
    asm volatile("redux.sync.max.s32 %0, %1, 0xffffffff;" : "=r"(im) : "r"(im));
    const int e = (im >> 23) - 127;
    const float sc = __int_as_float((127 - e) << 23);  // exact 2^-e
    r0 *= sc; r1 *= sc; r2 *= sc;
    return e;
}
__device__ __forceinline__ float ldg_cg(const float* p) {
    float v;
    asm volatile("ld.global.cg.f32 %0, [%1];" : "=f"(v) : "l"(p));
    return v;
}
__device__ __forceinline__ int ld_acq(const int* p) {
    int v;
    asm volatile("ld.global.acquire.gpu.b32 %0, [%1];" : "=r"(v) : "l"(p) : "memory");
    return v;
}

__global__ __launch_bounds__(256, 6)
void ctc_pipe_kernel(const int* __restrict__ y_true,
                     const float* __restrict__ y_pred,
                     float* __restrict__ out)
{
    // scan-CTA shared state (gather CTAs never touch it)
    __shared__ __align__(16) float bufF[32 * SP_];   // 4352 B
    __shared__ __align__(16) float bufB[32 * SP_];   // 4352 B
    __shared__ int   labs[L_];
    __shared__ float exA[66], exB[66];
    __shared__ int   exE[2];

    const int bid  = blockIdx.x;
    const int tid  = threadIdx.x;
    const int lane = tid & 31;
    const int wid  = tid >> 5;

    // ======================= GATHER CTAs (0 .. 2047) ========================
    if (bid < NGATHER) {
        __shared__ int labsx[33];
        const int b     = bid >> 3;
        const int chunk = (bid & 7) << 5;

        if (tid < 33)
            labsx[tid] = tid ? __ldg(y_true + b * L_ + tid - 1) : BLANK_;
        __syncthreads();

        const float* base = y_pred + ((size_t)b * T_ + chunk) * C_;

        float v[5];
        int   rr[5], cc[5];
#pragma unroll
        for (int i = 0; i < 5; ++i) {
            const int f = tid + i * 256;
            if (f < 1056) {
                const int row = f / 33;
                const int c   = f - 33 * row;
                rr[i] = row; cc[i] = c;
                v[i]  = ldg_cg(base + (size_t)row * C_ + labsx[c]);
            }
        }
        float* orow = g_scr + ((size_t)b * T_ + chunk) * SP_;
#pragma unroll
        for (int i = 0; i < 5; ++i) {
            const int f = tid + i * 256;
            if (f < 1056)
                orow[rr[i] * SP_ + cc[i]] = fmaf(v[i], PRE, EPS_S);
        }
        __threadfence();
        __syncthreads();
        if (tid == 0) atomicExch(&g_cflag[b][bid & 7], 1);
        return;
    }

    // ======================= SCAN CTAs (2048 .. 2303) =======================
    const int b = bid - NGATHER;

    if (tid < L_) labs[tid] = __ldg(y_true + b * L_ + tid);
    __syncthreads();

    const int s0 = 3 * lane, s1 = s0 + 1, s2 = s0 + 2;
    const int k0 = kidx(s0), k1 = kidx(s1), k2 = kidx(s2);

    // forward state (warp 0)
    const float fa0 = allow_fwd(s0, labs);
    const float fa1 = allow_fwd(s1, labs);
    const float fa2 = allow_fwd(s2, labs);
    float fr0 = 0.0f, fr1 = 0.0f, fr2 = 0.0f;
    int   fE = 0;

    // backward state (warp 1)
    const float ba0 = allow_bwd(s0, labs);
    const float ba1 = allow_bwd(s1, labs);
    const float ba2 = allow_bwd(s2, labs);
    float br0 = 0.0f, br1 = 0.0f, br2 = 0.0f;
    int   bE = 0;
    int   ilb = 0, ill = 0;
    {
        const int lab = labs[lane & 31];
        const unsigned nzm = __ballot_sync(FULLMASK, lab != 0);
        const int len = __popc(nzm);
        ilb = 2 * len;
        ill = 2 * len - 1;
        if (ill < 0) ill += S_;
    }

#define FSTEP(rr) {                                                  \
        const float* sr = bufF + (rr) * SP_;                         \
        const float p0 = sr[k0], p1 = sr[k1], p2 = sr[k2];           \
        float u1 = __shfl_up_sync(FULLMASK, fr1, 1);                 \
        float u2 = __shfl_up_sync(FULLMASK, fr2, 1);                 \
        u1 = lane ? u1 : 0.0f;                                       \
        u2 = lane ? u2 : 0.0f;                                       \
        const float n0 = p0 * fmaf(fa0, u1, fr0 + u2);               \
        const float n1 = p1 * fmaf(fa1, u2, fr1 + fr0);              \
        const float n2 = p2 * fmaf(fa2, fr0, fr2 + fr1);             \
        fr0 = n0; fr1 = n1; fr2 = n2; }

#define BSTEP(rr) {                                                  \
        const float* sr = bufB + (rr) * SP_;                         \
        const float p0 = sr[k0], p1 = sr[k1], p2 = sr[k2];           \
        const float u0 = __shfl_down_sync(FULLMASK, br0, 1);         \
        const float u1 = __shfl_down_sync(FULLMASK, br1, 1);         \
        const float B0 = fmaf(ba0, br2, br0 + br1);                  \
        const float B1 = fmaf(ba1, u0, br1 + br2);                   \
        const float B2 = fmaf(ba2, u1, br2 + u0);                    \
        br0 = p0 * B0; br1 = p1 * B1; br2 = p2 * B2; }

    for (int i = 0; i < 4; ++i) {
        // wait for fwd chunk i and bwd chunk 7-i
        if (tid == 0)  { while (!ld_acq(&g_cflag[b][i]))     __nanosleep(64); }
        if (tid == 32) { while (!ld_acq(&g_cflag[b][7 - i])) __nanosleep(64); }
        __syncthreads();

        // copy both 32-row chunks (contiguous in g_scr) into smem
        {
            const float4* srcF =
                (const float4*)(g_scr + ((size_t)b * T_ + 32 * i) * SP_);
            const float4* srcB =
                (const float4*)(g_scr + ((size_t)b * T_ + (224 - 32 * i)) * SP_);
            float4* dF = (float4*)bufF;
            float4* dB = (float4*)bufB;
            for (int x = tid; x < (32 * SP_) / 4; x += 256) {
                dF[x] = srcF[x];
                dB[x] = srcB[x];
            }
        }
        __syncthreads();

        if (wid == 0) {
            // forward over local rows (global t = 32*i + r)
            if (i == 0) {
                if (lane == 0) { fr0 = bufF[0]; fr1 = bufF[1]; }
#pragma unroll
                for (int j = 1; j < 8;  ++j) FSTEP(j);
                fE += renorm(fr0, fr1, fr2);
#pragma unroll
                for (int j = 8; j < 16; ++j) FSTEP(j);
                fE += renorm(fr0, fr1, fr2);
#pragma unroll
                for (int j = 16; j < 24; ++j) FSTEP(j);
                fE += renorm(fr0, fr1, fr2);
#pragma unroll
                for (int j = 24; j < 32; ++j) FSTEP(j);
                fE += renorm(fr0, fr1, fr2);
            } else {
#pragma unroll
                for (int g = 0; g < 4; ++g) {
#pragma unroll
                    for (int j = 0; j < 8; ++j) FSTEP(g * 8 + j);
                    fE += renorm(fr0, fr1, fr2);
                }
            }
        }
        else if (wid == 1) {
            // backward over local rows descending (global t = (224-32i) + r)
            if (i == 0) {
                // init at t=255 (local row 31)
                const float* sr = bufB + 31 * SP_;
                br0 = (s0 == ilb || s0 == ill) ? sr[k0] : 0.0f;
                br1 = (s1 == ilb || s1 == ill) ? sr[k1] : 0.0f;
                br2 = (s2 == ilb || s2 == ill) ? sr[k2] : 0.0f;
#pragma unroll
                for (int j = 30; j > 23; --j) BSTEP(j);
                bE += renorm(br0, br1, br2);
#pragma unroll
                for (int j = 23; j > 15; --j) BSTEP(j);
                bE += renorm(br0, br1, br2);
#pragma unroll
                for (int j = 15; j > 7; --j) BSTEP(j);
                bE += renorm(br0, br1, br2);
#pragma unroll
                for (int j = 7; j >= 0; --j) BSTEP(j);
                bE += renorm(br0, br1, br2);
            } else {
#pragma unroll
                for (int g = 0; g < 4; ++g) {
#pragma unroll
                    for (int j = 0; j < 8; ++j) BSTEP(31 - g * 8 - j);
                    bE += renorm(br0, br1, br2);
                }
            }
        }
        __syncthreads();
    }
#undef FSTEP
#undef BSTEP

    // publish boundary states
    if (wid == 0) {
        if (lane < 22) { exA[s0] = fr0; exA[s1] = fr1; exA[s2] = fr2; }
        if (lane == 0) exE[0] = fE;
    } else if (wid == 1) {
        // beta_127 combine (no p multiply) from c_128
        const float u0 = __shfl_down_sync(FULLMASK, br0, 1);
        const float u1 = __shfl_down_sync(FULLMASK, br1, 1);
        const float B0 = fmaf(ba0, br2, br0 + br1);
        const float B1 = fmaf(ba1, u0, br1 + br2);
        const float B2 = fmaf(ba2, u1, br2 + u0);
        if (lane < 22) { exB[s0] = B0; exB[s1] = B1; exB[s2] = B2; }
        if (lane == 0) exE[1] = bE;
    }
    __syncthreads();

    // combine: P = sum_s alpha_127[s] * beta_127[s]
    if (wid == 0) {
        float part = 0.0f;
        if (lane < 22)
            part = exA[s0] * exB[s0] + exA[s1] * exB[s1] + exA[s2] * exB[s2];
#pragma unroll
        for (int o = 16; o; o >>= 1)
            part += __shfl_xor_sync(FULLMASK, part, o);
        if (lane == 0) {
            const float LN2 = 0.6931471805599453f;
            out[b] = -(logf(part) +
                       (float)(exE[0] + exE[1] - PRE_E * T_) * LN2);
        }
    }
    // reset flags for the next graph replay
    if (tid < 8) g_cflag[b][tid] = 0;
}

extern "C" void kernel_launch(void* const* d_in, const int* in_sizes, int n_in,
                              void* d_out, int out_size)
{
    (void)n_in; (void)out_size;
    const int*   y_true;
    const float* y_pred;
    if (in_sizes[0] == B_ * L_) {
        y_true = (const int*)d_in[0];
        y_pred = (const float*)d_in[1];
    } else {
        y_true = (const int*)d_in[1];
        y_pred = (const float*)d_in[0];
    }
    ctc_pipe_kernel<<<NGATHER + B_, 256>>>(y_true, y_pred, (float*)d_out);
}

// round 9
// speedup vs baseline: 1.0468x; 1.0468x over previous
#include <cuda_runtime.h>

#define FULLMASK 0xffffffffu

constexpr int   B_     = 256;
constexpr int   T_     = 256;
constexpr int   C_     = 1024;
constexpr int   L_     = 32;
constexpr int   S_     = 65;      // 2*L+1 extended states
constexpr int   SP_    = 34;      // compact row: [blank, lab0..lab31, pad]
constexpr int   BLANK_ = C_ - 1;
constexpr float PRE    = 512.0f;  // 2^9 per-step prescale
constexpr int   PRE_E  = 9;
constexpr float EPS    = 1e-7f;
constexpr float EPS_S  = EPS * PRE;

// compact gathered probs, 8.9 MB (L2-resident between the two kernels)
__device__ float g_scr[(size_t)B_ * T_ * SP_];

__device__ __forceinline__ int kidx(int s) {
    return (s >= S_) ? 33 : ((s & 1) ? ((s >> 1) + 1) : 0);
}
__device__ __forceinline__ float allow_fwd(int s, const int* labs) {
    if (!(s & 1) || s >= S_) return 0.0f;
    const int j = (s - 1) >> 1;
    return (j == 0 || labs[j] != labs[j - 1]) ? 1.0f : 0.0f;
}
__device__ __forceinline__ float allow_bwd(int s, const int* labs) {
    if (!(s & 1) || (s + 2) > S_ - 1) return 0.0f;
    const int jn = (s + 1) >> 1, jp = (s - 1) >> 1;
    return (labs[jn] != labs[jp]) ? 1.0f : 0.0f;
}
// exact power-of-2 warp renorm via redux (all values >= 0)
__device__ __forceinline__ int renorm(float& r0, float& r1, float& r2) {
    float m = fmaxf(fmaxf(r0, r1), r2);
    int im = __float_as_int(m);
    asm volatile("redux.sync.max.s32 %0, %1, 0xffffffff;" : "=r"(im) : "r"(im));
    const int e = (im >> 23) - 127;
    const float sc = __int_as_float((127 - e) << 23);  // exact 2^-e
    r0 *= sc; r1 *= sc; r2 *= sc;
    return e;
}
__device__ __forceinline__ float ldg_cg(const float* p) {
    float v;
    asm volatile("ld.global.cg.f32 %0, [%1];" : "=f"(v) : "l"(p));
    return v;
}

// ---------------------------------------------------------------------------
// Kernel 1: saturating gather (unchanged; ~30 us, at random-access DRAM floor)
// ---------------------------------------------------------------------------
__global__ __launch_bounds__(256)
void ctc_gather_kernel(const int* __restrict__ y_true,
                       const float* __restrict__ y_pred)
{
    __shared__ int labsx[33];

    const int bid   = blockIdx.x;
    const int b     = bid >> 3;
    const int chunk = (bid & 7) << 5;
    const int tid   = threadIdx.x;

    if (tid < 33)
        labsx[tid] = tid ? __ldg(y_true + b * L_ + tid - 1) : BLANK_;
    __syncthreads();

    const float* base = y_pred + ((size_t)b * T_ + chunk) * C_;

    float v[5];
    int   rr[5], cc[5];
#pragma unroll
    for (int i = 0; i < 5; ++i) {
        const int f = tid + i * 256;
        if (f < 1056) {
            const int row = f / 33;
            const int c   = f - 33 * row;
            rr[i] = row; cc[i] = c;
            v[i]  = ldg_cg(base + (size_t)row * C_ + labsx[c]);
        }
    }
    float* orow = g_scr + ((size_t)b * T_ + chunk) * SP_;
#pragma unroll
    for (int i = 0; i < 5; ++i) {
        const int f = tid + i * 256;
        if (f < 1056)
            orow[rr[i] * SP_ + cc[i]] = fmaf(v[i], PRE, EPS_S);
    }
}

// ---------------------------------------------------------------------------
// Kernel 2: per-batch scan. Register-staged LDS, SEL-free chain.
// ---------------------------------------------------------------------------
__global__ __launch_bounds__(256)
void ctc_scan_kernel(const int* __restrict__ y_true,
                     float* __restrict__ out)
{
    __shared__ float slab[T_ * SP_];   // 34816 B
    __shared__ int   labs[L_];
    __shared__ float exA[66], exB[66];
    __shared__ int   exE[2];

    const int b    = blockIdx.x;
    const int tid  = threadIdx.x;
    const int lane = tid & 31;
    const int wid  = tid >> 5;

    if (tid < L_) labs[tid] = __ldg(y_true + b * L_ + tid);

    {
        const float4* src = (const float4*)(g_scr + (size_t)b * T_ * SP_);
        float4*       dst = (float4*)slab;
        for (int i = tid; i < (T_ * SP_) / 4; i += 256)
            dst[i] = src[i];
    }
    slab[tid * SP_ + 33] = 0.0f;   // dummy-state pad column
    __syncthreads();

    const int s0 = 3 * lane, s1 = s0 + 1, s2 = s0 + 2;
    const int k0 = kidx(s0), k1 = kidx(s1), k2 = kidx(s2);

    if (wid == 0) {
        // ---------------- forward: alpha_0 .. alpha_127 ----------------
        const float a0 = allow_fwd(s0, labs);
        float       a1 = allow_fwd(s1, labs);
        const float a2 = allow_fwd(s2, labs);
        const float mZ = lane ? 1.0f : 0.0f;   // masks u2 in n0 for lane 0
        if (lane == 0) a1 = 0.0f;              // alpha(-1) contribution = 0

        float r0 = 0.0f, r1 = 0.0f, r2 = 0.0f;
        if (lane == 0) { r0 = slab[0]; r1 = slab[1]; }

        int E = 0;
        float q[24];

#define FLOAD(j, tt) {                                               \
            const float* sr = slab + (tt) * SP_;                     \
            q[3*(j)]   = sr[k0];                                     \
            q[3*(j)+1] = sr[k1];                                     \
            q[3*(j)+2] = sr[k2]; }

#define FSTEP(j) {                                                   \
            const float u1 = __shfl_up_sync(FULLMASK, r1, 1);        \
            const float u2 = __shfl_up_sync(FULLMASK, r2, 1);        \
            const float n0 = q[3*(j)]   * fmaf(a0, u1, fmaf(mZ, u2, r0)); \
            const float n1 = q[3*(j)+1] * fmaf(a1, u2, r1 + r0);     \
            const float n2 = q[3*(j)+2] * fmaf(a2, r0, r2 + r1);     \
            r0 = n0; r1 = n1; r2 = n2; }

        // block 0: steps t=1..7 (7 steps)
#pragma unroll
        for (int j = 0; j < 7; ++j) FLOAD(j, 1 + j);
#pragma unroll
        for (int j = 0; j < 7; ++j) FSTEP(j);
        E += renorm(r0, r1, r2);

        // blocks: 15 x 8 steps, t = 8..127
        for (int tb = 8; tb < 128; tb += 8) {
#pragma unroll
            for (int j = 0; j < 8; ++j) FLOAD(j, tb + j);
#pragma unroll
            for (int j = 0; j < 8; ++j) FSTEP(j);
            E += renorm(r0, r1, r2);
        }
#undef FLOAD
#undef FSTEP

        if (lane < 22) { exA[s0] = r0; exA[s1] = r1; exA[s2] = r2; }
        if (lane == 0) exE[0] = E;
    }
    else if (wid == 1) {
        // ---------------- backward: c_t = p_t * beta_t, t = 255..128 ----
        const int lab = labs[lane];
        const unsigned nzm = __ballot_sync(FULLMASK, lab != 0);
        const int len = __popc(nzm);
        int ilb = 2 * len;
        int ill = 2 * len - 1;
        if (ill < 0) ill += S_;

        const float a0 = allow_bwd(s0, labs);
        const float a1 = allow_bwd(s1, labs);
        const float a2 = allow_bwd(s2, labs);

        float r0, r1, r2;
        {
            const float* sr = slab + 255 * SP_;
            r0 = (s0 == ilb || s0 == ill) ? sr[k0] : 0.0f;
            r1 = (s1 == ilb || s1 == ill) ? sr[k1] : 0.0f;
            r2 = (s2 == ilb || s2 == ill) ? sr[k2] : 0.0f;
        }

        int E = 0;
        float q[24];

#define BLOAD(j, tt) {                                               \
            const float* sr = slab + (tt) * SP_;                     \
            q[3*(j)]   = sr[k0];                                     \
            q[3*(j)+1] = sr[k1];                                     \
            q[3*(j)+2] = sr[k2]; }

#define BSTEP(j) {                                                   \
            const float u0 = __shfl_down_sync(FULLMASK, r0, 1);      \
            const float u1 = __shfl_down_sync(FULLMASK, r1, 1);      \
            const float n0 = q[3*(j)]   * fmaf(a0, r2, r0 + r1);     \
            const float n1 = q[3*(j)+1] * fmaf(a1, u0, r1 + r2);     \
            const float n2 = q[3*(j)+2] * fmaf(a2, u1, r2 + u0);     \
            r0 = n0; r1 = n1; r2 = n2; }

        // block 0: steps t=254..248 (7 steps)
#pragma unroll
        for (int j = 0; j < 7; ++j) BLOAD(j, 254 - j);
#pragma unroll
        for (int j = 0; j < 7; ++j) BSTEP(j);
        E += renorm(r0, r1, r2);

        // blocks: 15 x 8 steps, t = 247..128
        for (int tb = 247; tb >= 135; tb -= 8) {
#pragma unroll
            for (int j = 0; j < 8; ++j) BLOAD(j, tb - j);
#pragma unroll
            for (int j = 0; j < 8; ++j) BSTEP(j);
            E += renorm(r0, r1, r2);
        }
#undef BLOAD
#undef BSTEP

        // beta_127 combine (no p multiply) from c_128
        const float u0 = __shfl_down_sync(FULLMASK, r0, 1);
        const float u1 = __shfl_down_sync(FULLMASK, r1, 1);
        const float B0 = fmaf(a0, r2, r0 + r1);
        const float B1 = fmaf(a1, u0, r1 + r2);
        const float B2 = fmaf(a2, u1, r2 + u0);
        if (lane < 22) { exB[s0] = B0; exB[s1] = B1; exB[s2] = B2; }
        if (lane == 0) exE[1] = E;
    }
    __syncthreads();

    // combine: P = sum_s alpha_127[s] * beta_127[s]
    if (wid == 0) {
        float part = 0.0f;
        if (lane < 22)
            part = exA[s0] * exB[s0] + exA[s1] * exB[s1] + exA[s2] * exB[s2];
#pragma unroll
        for (int o = 16; o; o >>= 1)
            part += __shfl_xor_sync(FULLMASK, part, o);
        if (lane == 0) {
            const float LN2 = 0.6931471805599453f;
            out[b] = -(logf(part) +
                       (float)(exE[0] + exE[1] - PRE_E * T_) * LN2);
        }
    }
}

extern "C" void kernel_launch(void* const* d_in, const int* in_sizes, int n_in,
                              void* d_out, int out_size)
{
    (void)n_in; (void)out_size;
    const int*   y_true;
    const float* y_pred;
    if (in_sizes[0] == B_ * L_) {
        y_true = (const int*)d_in[0];
        y_pred = (const float*)d_in[1];
    } else {
        y_true = (const int*)d_in[1];
        y_pred = (const float*)d_in[0];
    }
    ctc_gather_kernel<<<B_ * 8, 256>>>(y_true, y_pred);
    ctc_scan_kernel<<<B_, 256>>>(y_true, (float*)d_out);
}